// round 2
// baseline (speedup 1.0000x reference)
#include <cuda_runtime.h>
#include <cuda_bf16.h>

// Problem constants
#define NSEQ 1024
#define HID  100
#define G4   400      // 4*HID
#define WD   100
#define TD   25
#define IN0  125      // WD+TD
#define LBL  40
#define NTHR 416      // 104 padded units * 4 gates
#define EPSV 1e-20f

// ---------------- device scratch (no allocations allowed) ----------------
__device__ float d_Wr0[HID * NTHR];   // recurrent weights layer0, [k][tid]
__device__ float d_Wr1[HID * NTHR];
__device__ float d_Wt0[IN0 * G4];     // W_ih0 transposed: [k][r]
__device__ float d_Wt1[HID * G4];     // W_ih1 transposed
__device__ float d_G0[NSEQ * G4];     // input preactivations layer0
__device__ float d_G1[NSEQ * G4];
__device__ float d_h0[NSEQ * HID];
__device__ float d_h1[NSEQ * HID];
__device__ float d_u[HID];
__device__ float d_v[HID];
__device__ float d_cval;
__device__ float d_ea[NSEQ];
__device__ float d_eb[NSEQ];
__device__ float d_f[NSEQ];

// ---------------- f32x2 helpers ----------------
__device__ __forceinline__ void fma2(unsigned long long& d,
                                     unsigned long long a,
                                     unsigned long long b) {
    asm("fma.rn.f32x2 %0, %1, %2, %0;" : "+l"(d) : "l"(a), "l"(b));
}
__device__ __forceinline__ void add2(unsigned long long& d,
                                     unsigned long long a,
                                     unsigned long long b) {
    asm("add.rn.f32x2 %0, %1, %2;" : "=l"(d) : "l"(a), "l"(b));
}
__device__ __forceinline__ unsigned long long pack2(float lo, float hi) {
    unsigned long long r;
    unsigned int ulo = __float_as_uint(lo), uhi = __float_as_uint(hi);
    asm("mov.b64 %0, {%1, %2};" : "=l"(r) : "r"(ulo), "r"(uhi));
    return r;
}
__device__ __forceinline__ float sum2(unsigned long long v) {
    unsigned int lo, hi;
    asm("mov.b64 {%0, %1}, %2;" : "=r"(lo), "=r"(hi) : "l"(v));
    return __uint_as_float(lo) + __uint_as_float(hi);
}
__device__ __forceinline__ float tanhfast(float x) {
    float e = __expf(2.f * x);
    return __fdividef(e - 1.f, e + 1.f);
}

// ---------------- prep: weight relayouts (parallel, one-shot) ----------------
__global__ void prep_kernel(const float* __restrict__ W_hh0,
                            const float* __restrict__ W_hh1,
                            const float* __restrict__ W_ih0,
                            const float* __restrict__ W_ih1) {
    int idx = blockIdx.x * blockDim.x + threadIdx.x;
    const int n_wr  = HID * NTHR;       // 41600
    const int n_wt0 = IN0 * G4;         // 50000
    const int n_wt1 = HID * G4;         // 40000
    if (idx < n_wr) {
        int k = idx / NTHR, t = idx % NTHR;
        int j = t >> 2, g = t & 3;
        d_Wr0[idx] = (j < HID) ? W_hh0[(g * HID + j) * HID + k] : 0.f;
    } else if (idx < 2 * n_wr) {
        int rel = idx - n_wr;
        int k = rel / NTHR, t = rel % NTHR;
        int j = t >> 2, g = t & 3;
        d_Wr1[rel] = (j < HID) ? W_hh1[(g * HID + j) * HID + k] : 0.f;
    } else if (idx < 2 * n_wr + n_wt0) {
        int rel = idx - 2 * n_wr;
        int k = rel / G4, r = rel % G4;
        d_Wt0[rel] = W_ih0[r * IN0 + k];
    } else if (idx < 2 * n_wr + n_wt0 + n_wt1) {
        int rel = idx - 2 * n_wr - n_wt0;
        int k = rel / G4, r = rel % G4;
        d_Wt1[rel] = W_ih1[r * HID + k];
    }
}

// ---------------- G0: emb @ W_ih0^T + biases (parallel over t) ----------------
__global__ __launch_bounds__(NTHR) void g0_kernel(
    const int* __restrict__ wi, const int* __restrict__ ti,
    const float* __restrict__ word_table, const float* __restrict__ tag_table,
    const float* __restrict__ b_ih, const float* __restrict__ b_hh) {
    __shared__ float embs[8][IN0 + 3];
    int t0 = blockIdx.x * 8;
    int tid = threadIdx.x;
    for (int idx = tid; idx < 8 * IN0; idx += NTHR) {
        int tt = idx / IN0, k = idx % IN0;
        int t = t0 + tt;
        embs[tt][k] = (k < WD) ? word_table[wi[t] * WD + k]
                               : tag_table[ti[t] * TD + (k - WD)];
    }
    __syncthreads();
    int r = tid;
    if (r < G4) {
        float bias = b_ih[r] + b_hh[r];
        float acc[8];
#pragma unroll
        for (int tt = 0; tt < 8; tt++) acc[tt] = bias;
        for (int k = 0; k < IN0; k++) {
            float w = d_Wt0[k * G4 + r];
#pragma unroll
            for (int tt = 0; tt < 8; tt++) acc[tt] += w * embs[tt][k];
        }
#pragma unroll
        for (int tt = 0; tt < 8; tt++) d_G0[(t0 + tt) * G4 + r] = acc[tt];
    }
}

// ---------------- G1: h0 @ W_ih1^T + biases ----------------
__global__ __launch_bounds__(NTHR) void g1_kernel(
    const float* __restrict__ b_ih, const float* __restrict__ b_hh) {
    __shared__ float embs[8][HID + 4];
    int t0 = blockIdx.x * 8;
    int tid = threadIdx.x;
    for (int idx = tid; idx < 8 * HID; idx += NTHR) {
        int tt = idx / HID, k = idx % HID;
        embs[tt][k] = d_h0[(t0 + tt) * HID + k];
    }
    __syncthreads();
    int r = tid;
    if (r < G4) {
        float bias = b_ih[r] + b_hh[r];
        float acc[8];
#pragma unroll
        for (int tt = 0; tt < 8; tt++) acc[tt] = bias;
        for (int k = 0; k < HID; k++) {
            float w = d_Wt1[k * G4 + r];
#pragma unroll
            for (int tt = 0; tt < 8; tt++) acc[tt] += w * embs[tt][k];
        }
#pragma unroll
        for (int tt = 0; tt < 8; tt++) d_G1[(t0 + tt) * G4 + r] = acc[tt];
    }
}

// ---------------- persistent single-CTA LSTM recurrence ----------------
// thread tid = j*4 + g  (j = hidden unit 0..103 padded, g = gate i/f/g/o)
__global__ void __launch_bounds__(NTHR, 1) rec_kernel(int layer) {
    __shared__ __align__(16) float hs[2][112];
    const float* __restrict__ Wr = layer ? d_Wr1 : d_Wr0;
    const float* __restrict__ G  = layer ? d_G1  : d_G0;
    float* __restrict__ hout     = layer ? d_h1  : d_h0;

    int tid = threadIdx.x;
    int g = tid & 3, j = tid >> 2;
    bool active = (j < HID);
    int gidx = g * HID + j;

    // load this thread's recurrent row into registers, packed as f32x2
    unsigned long long w2[50];
#pragma unroll
    for (int k = 0; k < 50; k++) {
        float lo = Wr[(2 * k) * NTHR + tid];
        float hi = Wr[(2 * k + 1) * NTHR + tid];
        w2[k] = pack2(lo, hi);
    }
    if (tid < 112) { hs[0][tid] = 0.f; hs[1][tid] = 0.f; }
    float c = 0.f;
    float gin = active ? G[gidx] : 0.f;
    unsigned int lanebase = (tid & 31) & ~3u;
    __syncthreads();

    for (int t = 0; t < NSEQ; t++) {
        // prefetch next step's input preactivation (hides L2 latency)
        float gnext = (active && t < NSEQ - 1) ? G[(t + 1) * G4 + gidx] : 0.f;

        const unsigned long long* h2 =
            reinterpret_cast<const unsigned long long*>(hs[t & 1]);
        unsigned long long a0 = 0ull, a1 = 0ull, a2 = 0ull, a3 = 0ull;
#pragma unroll
        for (int k = 0; k < 48; k += 4) {
            fma2(a0, w2[k],     h2[k]);
            fma2(a1, w2[k + 1], h2[k + 1]);
            fma2(a2, w2[k + 2], h2[k + 2]);
            fma2(a3, w2[k + 3], h2[k + 3]);
        }
        fma2(a0, w2[48], h2[48]);
        fma2(a1, w2[49], h2[49]);
        unsigned long long s01, s23;
        add2(s01, a0, a1);
        add2(s23, a2, a3);
        add2(s01, s01, s23);
        float pre = sum2(s01) + gin;

        // branchless activation: g==2 -> tanh, else sigmoid
        float xin = (g == 2) ? 2.f * pre : -pre;
        float e = __expf(xin);
        float num = (g == 2) ? (e - 1.f) : 1.f;
        float act = __fdividef(num, e + 1.f);

        // gather the 4 gates of this unit (4-lane aligned group)
        float vi = __shfl_sync(0xffffffffu, act, lanebase + 0);
        float vf = __shfl_sync(0xffffffffu, act, lanebase + 1);
        float vg = __shfl_sync(0xffffffffu, act, lanebase + 2);
        float vo = __shfl_sync(0xffffffffu, act, lanebase + 3);

        if (g == 0) {
            c = vf * c + vi * vg;
            float h = vo * tanhfast(c);
            hs[(t + 1) & 1][j] = h;
            if (active) hout[t * HID + j] = h;
        }
        gin = gnext;
        __syncthreads();
    }
}

// ---------------- rank-1 collapse of the pairwise scorer ----------------
__global__ void uv_kernel(const float* __restrict__ W_h2h,
                          const float* __restrict__ b_h2h,
                          const float* __restrict__ W_sc,
                          const float* __restrict__ b_sc) {
    int q = threadIdx.x;
    if (q < HID) {
        float u = 0.f, v = 0.f;
        for (int p = 0; p < HID; p++) {
            float s = W_sc[p];
            u += s * W_h2h[p * (2 * HID) + q];
            v += s * W_h2h[p * (2 * HID) + HID + q];
        }
        d_u[q] = u;
        d_v[q] = v;
    }
    if (q == HID) {
        float cc = b_sc[0];
        for (int p = 0; p < HID; p++) cc += W_sc[p] * b_h2h[p];
        d_cval = cc;
    }
}

__global__ void ab_kernel() {
    int i = blockIdx.x * blockDim.x + threadIdx.x;
    if (i >= NSEQ) return;
    const float* h = &d_h1[i * HID];
    float a = 0.f, b = 0.f;
#pragma unroll 4
    for (int q = 0; q < HID; q++) {
        float hv = h[q];
        a += hv * d_u[q];
        b += hv * d_v[q];
    }
    d_ea[i] = __expf(a);
    d_eb[i] = __expf(b + d_cval);
}

__global__ void sf_kernel() {
    __shared__ float red[NSEQ];
    int t = threadIdx.x;
    red[t] = d_ea[t];
    __syncthreads();
    for (int s = NSEQ / 2; s > 32; s >>= 1) {
        if (t < s) red[t] += red[t + s];
        __syncthreads();
    }
    float S;
    if (t < 32) {
        float x = red[t] + red[t + 32];
        for (int o = 16; o > 0; o >>= 1)
            x += __shfl_down_sync(0xffffffffu, x, o);
        if (t == 0) red[0] = x;
    }
    __syncthreads();
    S = red[0];
    float e = d_eb[t];
    d_f[t] = __fdividef(e, e * S + EPSV);
}

// one block per row; float4 stores for the 4MB HBM write
__global__ __launch_bounds__(256) void scores_kernel(float* __restrict__ out) {
    int i = blockIdx.x;
    float eai = d_ea[i];
    const float4* f4 = reinterpret_cast<const float4*>(d_f);
    float4* o4 = reinterpret_cast<float4*>(out + (size_t)i * NSEQ);
    int j = threadIdx.x;  // 256 threads x float4 = 1024 floats
    float4 v = f4[j];
    v.x *= eai; v.y *= eai; v.z *= eai; v.w *= eai;
    o4[j] = v;
}

__global__ void labels_kernel(const float* __restrict__ W_lab,
                              const float* __restrict__ b_lab,
                              float* __restrict__ out) {
    __shared__ float hrow[HID];
    __shared__ float el[LBL];
    __shared__ float denom;
    int t = blockIdx.x;  // 0..NSEQ-2, uses h[t+1]
    int tid = threadIdx.x;
    if (tid < HID) hrow[tid] = d_h1[(t + 1) * HID + tid];
    __syncthreads();
    if (tid < LBL) {
        float a = b_lab[tid];
        for (int q = 0; q < HID; q++) a += hrow[q] * W_lab[tid * HID + q];
        el[tid] = __expf(a);
    }
    __syncthreads();
    if (tid == 0) {
        float s = 0.f;
        for (int l = 0; l < LBL; l++) s += el[l];
        denom = s + EPSV;
    }
    __syncthreads();
    if (tid < LBL) out[NSEQ * NSEQ + t * LBL + tid] = el[tid] / denom;
}

// ---------------- launch ----------------
extern "C" void kernel_launch(void* const* d_in, const int* in_sizes, int n_in,
                              void* d_out, int out_size) {
    const int*   wi         = (const int*)d_in[0];
    const int*   ti         = (const int*)d_in[1];
    const float* word_table = (const float*)d_in[2];
    const float* tag_table  = (const float*)d_in[3];
    const float* W_ih0      = (const float*)d_in[4];
    const float* W_hh0      = (const float*)d_in[5];
    const float* b_ih0      = (const float*)d_in[6];
    const float* b_hh0      = (const float*)d_in[7];
    const float* W_ih1      = (const float*)d_in[8];
    const float* W_hh1      = (const float*)d_in[9];
    const float* b_ih1      = (const float*)d_in[10];
    const float* b_hh1      = (const float*)d_in[11];
    const float* W_h2h      = (const float*)d_in[12];
    const float* b_h2h      = (const float*)d_in[13];
    const float* W_sc       = (const float*)d_in[14];
    const float* b_sc       = (const float*)d_in[15];
    const float* W_lab      = (const float*)d_in[16];
    const float* b_lab      = (const float*)d_in[17];
    float* out = (float*)d_out;

    const int prep_total = 2 * (HID * NTHR) + IN0 * G4 + HID * G4;
    prep_kernel<<<(prep_total + 255) / 256, 256>>>(W_hh0, W_hh1, W_ih0, W_ih1);
    g0_kernel<<<NSEQ / 8, NTHR>>>(wi, ti, word_table, tag_table, b_ih0, b_hh0);
    rec_kernel<<<1, NTHR>>>(0);
    g1_kernel<<<NSEQ / 8, NTHR>>>(b_ih1, b_hh1);
    rec_kernel<<<1, NTHR>>>(1);
    uv_kernel<<<1, 128>>>(W_h2h, b_h2h, W_sc, b_sc);
    ab_kernel<<<NSEQ / 256, 256>>>();
    sf_kernel<<<1, NSEQ>>>();
    scores_kernel<<<NSEQ, 256>>>(out);
    labels_kernel<<<NSEQ - 1, 128>>>(W_lab, b_lab, out);
}